// round 12
// baseline (speedup 1.0000x reference)
#include <cuda_runtime.h>
#include <cstdint>

#define N_BINS 1000
#define EPS_F 1e-4f
#define TPB 256
// ~60-reg kernel -> 4 resident blocks/SM; 148 SMs x 4 = 592 = one wave.
#define NBLOCKS 592

// sm_103a: L2::evict_last requires 256-bit loads (.v4.b64).
// Pins the 100MB read-once-per-launch index stream in L2 across graph replays.
__device__ __forceinline__ void ld256_evict_last(const void* p,
                                                 unsigned long long* w) {
    asm volatile("ld.global.nc.L2::evict_last.v4.b64 {%0,%1,%2,%3}, [%4];"
                 : "=l"(w[0]), "=l"(w[1]), "=l"(w[2]), "=l"(w[3])
                 : "l"(p));
}

// Extract int32 word j (0..23) from the 12-u64 pair buffer.
__device__ __forceinline__ unsigned pair_word(const unsigned long long* w,
                                              int j) {
    unsigned long long v = w[j >> 1];
    return (j & 1) ? (unsigned)(v >> 32) : (unsigned)v;
}

// ---------------------------------------------------------------------------
// Fused persistent kernel:
//   1) per-block build of the 3x1000 sigmoid table in shared memory
//   2) depth-2 pipelined grid-stride loop over PAIRS of quads:
//      8 rows = 96B = 3 x 32B evict_last loads per pair, unpacked from u64,
//      gathered from the smem table, stored as 2 x float4 (__stcs).
// ---------------------------------------------------------------------------
__global__ void __launch_bounds__(TPB, 4)
pm_fused_kernel(const float* __restrict__ bin_centers,
                const float* __restrict__ lower_bounds,
                const float* __restrict__ upper_bounds,
                const char* __restrict__ idx_bytes,
                float4* __restrict__ out_v,
                const int* __restrict__ idx_s,   // scalar view for tail
                float* __restrict__ out_s,
                long long n_pairs, long long n_rows) {
    __shared__ float sS[3 * N_BINS];

    // ---- table build: S[j][b] = sigmoid((ub_j - logit(t_b)) * inv_j) ----
    float hi[3], inv[3];
#pragma unroll
    for (int j = 0; j < 3; j++) {
        float l = lower_bounds[j];
        float u = upper_bounds[j];
        float lo = fminf(l, u);
        float h  = fmaxf(l, u);
        hi[j]  = h;
        inv[j] = 1.0f / (h - lo + EPS_F);
    }
    for (int b = threadIdx.x; b < N_BINS; b += TPB) {
        float t = __ldg(bin_centers + b);
        float g = __logf(t / (1.0f - t));
#pragma unroll
        for (int j = 0; j < 3; j++) {
            float x = (hi[j] - g) * inv[j];
            sS[j * N_BINS + b] = 1.0f / (1.0f + __expf(-x));
        }
    }
    __syncthreads();

    const float* __restrict__ S0 = sS;
    const float* __restrict__ S1 = sS + N_BINS;
    const float* __restrict__ S2 = sS + 2 * N_BINS;

    // ---- depth-2 pipelined grid-stride loop over pairs (8 rows each) ----
    const long long stride = (long long)gridDim.x * TPB;
    long long p0 = (long long)blockIdx.x * TPB + threadIdx.x;
    long long p1 = p0 + stride;
    long long p2 = p1 + stride;

    unsigned long long A[12], B[12];

    if (p0 < n_pairs) {
        const char* b = idx_bytes + p0 * 96;
        ld256_evict_last(b,      A);
        ld256_evict_last(b + 32, A + 4);
        ld256_evict_last(b + 64, A + 8);
    }
    if (p1 < n_pairs) {
        const char* b = idx_bytes + p1 * 96;
        ld256_evict_last(b,      B);
        ld256_evict_last(b + 32, B + 4);
        ld256_evict_last(b + 64, B + 8);
    }

    while (p2 < n_pairs) {
        unsigned long long C[12];
        {
            const char* b = idx_bytes + p2 * 96;
            ld256_evict_last(b,      C);
            ld256_evict_last(b + 32, C + 4);
            ld256_evict_last(b + 64, C + 8);
        }

        float r[8];
#pragma unroll
        for (int i = 0; i < 8; i++) {
            unsigned a = pair_word(A, 3 * i + 0);
            unsigned bb = pair_word(A, 3 * i + 1);
            unsigned cc = pair_word(A, 3 * i + 2);
            r[i] = S0[a] * S1[bb] * S2[cc];
        }
        float4 o0 = {r[0], r[1], r[2], r[3]};
        float4 o1 = {r[4], r[5], r[6], r[7]};
        __stcs(out_v + 2 * p0,     o0);
        __stcs(out_v + 2 * p0 + 1, o1);

#pragma unroll
        for (int k = 0; k < 12; k++) { A[k] = B[k]; B[k] = C[k]; }
        p0 = p1; p1 = p2; p2 += stride;
    }

    // Drain the (up to) two pairs already in registers.
    if (p0 < n_pairs) {
        float r[8];
#pragma unroll
        for (int i = 0; i < 8; i++) {
            unsigned a = pair_word(A, 3 * i + 0);
            unsigned bb = pair_word(A, 3 * i + 1);
            unsigned cc = pair_word(A, 3 * i + 2);
            r[i] = S0[a] * S1[bb] * S2[cc];
        }
        float4 o0 = {r[0], r[1], r[2], r[3]};
        float4 o1 = {r[4], r[5], r[6], r[7]};
        __stcs(out_v + 2 * p0,     o0);
        __stcs(out_v + 2 * p0 + 1, o1);
    }
    if (p1 < n_pairs) {
        float r[8];
#pragma unroll
        for (int i = 0; i < 8; i++) {
            unsigned a = pair_word(B, 3 * i + 0);
            unsigned bb = pair_word(B, 3 * i + 1);
            unsigned cc = pair_word(B, 3 * i + 2);
            r[i] = S0[a] * S1[bb] * S2[cc];
        }
        float4 o0 = {r[0], r[1], r[2], r[3]};
        float4 o1 = {r[4], r[5], r[6], r[7]};
        __stcs(out_v + 2 * p1,     o0);
        __stcs(out_v + 2 * p1 + 1, o1);
    }

    // ---- scalar tail (rows past n_pairs*8; zero for this problem) ----
    if (blockIdx.x == 0) {
        for (long long r = n_pairs * 8 + threadIdx.x; r < n_rows; r += TPB) {
            int a = idx_s[3 * r + 0];
            int b = idx_s[3 * r + 1];
            int c = idx_s[3 * r + 2];
            out_s[r] = S0[a] * S1[b] * S2[c];
        }
    }
}

extern "C" void kernel_launch(void* const* d_in, const int* in_sizes, int n_in,
                              void* d_out, int out_size) {
    const float* bin_centers  = (const float*)d_in[0];
    const int*   obs_idx      = (const int*)d_in[1];   // JAX x64-off: int64 -> int32
    const float* lower_bounds = (const float*)d_in[2];
    const float* upper_bounds = (const float*)d_in[3];
    float* out = (float*)d_out;

    long long n = out_size;
    long long n_pairs = n / 8;

    int blocks = NBLOCKS;
    long long max_needed = (n_pairs + TPB - 1) / TPB;
    if (max_needed < 1) max_needed = 1;
    if (max_needed < blocks) blocks = (int)max_needed;

    pm_fused_kernel<<<blocks, TPB>>>(bin_centers, lower_bounds, upper_bounds,
                                     (const char*)obs_idx, (float4*)out,
                                     obs_idx, out, n_pairs, n);
}

// round 13
// speedup vs baseline: 2.0599x; 2.0599x over previous
#include <cuda_runtime.h>
#include <cstdint>

#define N_BINS 1000
#define EPS_F 1e-4f
#define TPB 256
// 48-reg kernel -> 5 resident blocks/SM; 148 SMs x 5 = 740 = one wave.
#define NBLOCKS 740

// ---------------------------------------------------------------------------
// Fused persistent kernel (measured best, round 10: 25.3us total):
//   1) per-block build of the 3x1000 sigmoid table in shared memory
//   2) depth-2 software-pipelined grid-stride gather-product loop
// Streaming cache hints: __ldcs on the read-once index stream, __stcs on the
// write-once output stream (keeps L2 clean between graph replays).
//
// Quad layout (3 x uint4 per 4 rows of 3 int32 indices):
//   v0 = [i0.a, i0.b, i0.c, i1.a]
//   v1 = [i1.b, i1.c, i2.a, i2.b]
//   v2 = [i2.c, i3.a, i3.b, i3.c]
// ---------------------------------------------------------------------------
__global__ void __launch_bounds__(TPB, 5)
pm_fused_kernel(const float* __restrict__ bin_centers,
                const float* __restrict__ lower_bounds,
                const float* __restrict__ upper_bounds,
                const uint4* __restrict__ idx_v,
                float4* __restrict__ out_v,
                const int* __restrict__ idx_s,   // scalar view for tail
                float* __restrict__ out_s,
                int n_quads, int n_rows) {
    __shared__ float sS[3 * N_BINS];

    // ---- table build: S[j][b] = sigmoid((ub_j - logit(t_b)) * inv_j) ----
    float hi[3], inv[3];
#pragma unroll
    for (int j = 0; j < 3; j++) {
        float l = lower_bounds[j];
        float u = upper_bounds[j];
        float lo = fminf(l, u);
        float h  = fmaxf(l, u);
        hi[j]  = h;
        inv[j] = 1.0f / (h - lo + EPS_F);
    }
    for (int b = threadIdx.x; b < N_BINS; b += TPB) {
        float t = __ldg(bin_centers + b);
        float g = __logf(t / (1.0f - t));
#pragma unroll
        for (int j = 0; j < 3; j++) {
            float x = (hi[j] - g) * inv[j];
            sS[j * N_BINS + b] = 1.0f / (1.0f + __expf(-x));
        }
    }
    __syncthreads();

    const float* __restrict__ S0 = sS;
    const float* __restrict__ S1 = sS + N_BINS;
    const float* __restrict__ S2 = sS + 2 * N_BINS;

    // ---- depth-2 pipelined grid-stride loop over quads ----
    const int stride = gridDim.x * TPB;
    int q0 = blockIdx.x * TPB + threadIdx.x;
    int q1 = q0 + stride;
    int q2 = q1 + stride;

    uint4 a0, a1, a2;   // quad q0
    uint4 b0, b1, b2;   // quad q1

    if (q0 < n_quads) {
        const uint4* p = idx_v + (size_t)q0 * 3;
        a0 = __ldcs(p + 0);
        a1 = __ldcs(p + 1);
        a2 = __ldcs(p + 2);
    }
    if (q1 < n_quads) {
        const uint4* p = idx_v + (size_t)q1 * 3;
        b0 = __ldcs(p + 0);
        b1 = __ldcs(p + 1);
        b2 = __ldcs(p + 2);
    }

    while (q2 < n_quads) {
        // Prefetch quad q2 (two iterations ahead of the one being computed).
        const uint4* p = idx_v + (size_t)q2 * 3;
        uint4 c0 = __ldcs(p + 0);
        uint4 c1 = __ldcs(p + 1);
        uint4 c2 = __ldcs(p + 2);

        float4 o;
        o.x = S0[a0.x] * S1[a0.y] * S2[a0.z];
        o.y = S0[a0.w] * S1[a1.x] * S2[a1.y];
        o.z = S0[a1.z] * S1[a1.w] * S2[a2.x];
        o.w = S0[a2.y] * S1[a2.z] * S2[a2.w];
        __stcs(out_v + q0, o);

        a0 = b0; a1 = b1; a2 = b2;
        b0 = c0; b1 = c1; b2 = c2;
        q0 = q1; q1 = q2; q2 += stride;
    }

    // Drain: at most two quads left in registers.
    if (q0 < n_quads) {
        float4 o;
        o.x = S0[a0.x] * S1[a0.y] * S2[a0.z];
        o.y = S0[a0.w] * S1[a1.x] * S2[a1.y];
        o.z = S0[a1.z] * S1[a1.w] * S2[a2.x];
        o.w = S0[a2.y] * S1[a2.z] * S2[a2.w];
        __stcs(out_v + q0, o);
    }
    if (q1 < n_quads) {
        float4 o;
        o.x = S0[b0.x] * S1[b0.y] * S2[b0.z];
        o.y = S0[b0.w] * S1[b1.x] * S2[b1.y];
        o.z = S0[b1.z] * S1[b1.w] * S2[b2.x];
        o.w = S0[b2.y] * S1[b2.z] * S2[b2.w];
        __stcs(out_v + q1, o);
    }

    // ---- scalar tail (n_rows % 4 != 0; never taken for this problem) ----
    int tail_start = n_quads * 4;
    if (blockIdx.x == 0) {
        int r = tail_start + threadIdx.x;
        if (r < n_rows) {
            int a = idx_s[3 * (size_t)r + 0];
            int b = idx_s[3 * (size_t)r + 1];
            int c = idx_s[3 * (size_t)r + 2];
            out_s[r] = S0[a] * S1[b] * S2[c];
        }
    }
}

extern "C" void kernel_launch(void* const* d_in, const int* in_sizes, int n_in,
                              void* d_out, int out_size) {
    const float* bin_centers  = (const float*)d_in[0];
    const int*   obs_idx      = (const int*)d_in[1];   // JAX x64-off: int64 -> int32
    const float* lower_bounds = (const float*)d_in[2];
    const float* upper_bounds = (const float*)d_in[3];
    float* out = (float*)d_out;

    int n = out_size;
    int n_quads = n / 4;

    int blocks = NBLOCKS;
    int max_needed = (n_quads + TPB - 1) / TPB;
    if (max_needed < 1) max_needed = 1;
    if (blocks > max_needed) blocks = max_needed;

    pm_fused_kernel<<<blocks, TPB>>>(bin_centers, lower_bounds, upper_bounds,
                                     (const uint4*)obs_idx, (float4*)out,
                                     obs_idx, out, n_quads, n);
}